// round 5
// baseline (speedup 1.0000x reference)
#include <cuda_runtime.h>
#include <cuda_fp16.h>
#include <math.h>
#include <stdint.h>

#define N_ROWS 32768
#define DIM    256
#define KCB    8192
#define NBLK_GATHER 4096
#define GAP_THR 5e-3f

// ---------------------------------------------------------------------------
// scratch (device globals; no cudaMalloc allowed)
__device__ __half g_Xh[(size_t)N_ROWS * DIM];
__device__ __half g_Eh[(size_t)KCB * DIM];     // transposed: [code][dim]
__device__ float g_cnorm[KCB];
__device__ int   g_idx[N_ROWS];
__device__ int   g_flag[N_ROWS];
__device__ int   g_hist[KCB];
__device__ float g_partials[NBLK_GATHER];

// ---------------------------------------------------------------------------
__device__ __forceinline__ uint32_t smem_u32(const void* p) {
    uint32_t a;
    asm("{ .reg .u64 t; cvta.to.shared.u64 t, %1; cvt.u32.u64 %0, t; }"
        : "=r"(a) : "l"(p));
    return a;
}

#define CP_ASYNC16(s, g) \
    asm volatile("cp.async.cg.shared.global [%0], [%1], 16;" :: "r"(s), "l"(g) : "memory")
#define CP_COMMIT()  asm volatile("cp.async.commit_group;" ::: "memory")
#define CP_WAIT1()   asm volatile("cp.async.wait_group 1;" ::: "memory")
#define CP_WAIT0()   asm volatile("cp.async.wait_group 0;" ::: "memory")

__device__ __forceinline__ void ldsm4(uint32_t* r, uint32_t addr) {
    asm volatile("ldmatrix.sync.aligned.m8n8.x4.shared.b16 {%0,%1,%2,%3}, [%4];"
                 : "=r"(r[0]), "=r"(r[1]), "=r"(r[2]), "=r"(r[3]) : "r"(addr));
}

__device__ __forceinline__ void mma16816(float* c, const uint32_t* a, uint32_t b0, uint32_t b1) {
    asm volatile(
        "mma.sync.aligned.m16n8k16.row.col.f32.f16.f16.f32 "
        "{%0,%1,%2,%3}, {%4,%5,%6,%7}, {%8,%9}, {%0,%1,%2,%3};"
        : "+f"(c[0]), "+f"(c[1]), "+f"(c[2]), "+f"(c[3])
        : "r"(a[0]), "r"(a[1]), "r"(a[2]), "r"(a[3]), "r"(b0), "r"(b1));
}

// smem layout: A 128 rows x 264 fp16 (stride 528B, 33 chunks ≡ 1 mod 8),
// B double-buffered 128 codes x 136 fp16 (stride 272B, 17 chunks ≡ 1 mod 8)
#define SA_BYTES 528
#define SB_BYTES 272
#define SM_A     0
#define SM_B     (128 * SA_BYTES)       // 67584
#define SB_BUF   (128 * SB_BYTES)       // 34816
#define SMEM_TOTAL (SM_B + 2 * SB_BUF)  // 137216

// ---------------------------------------------------------------------------
__global__ void zero_hist_kernel() {
    int t = blockIdx.x * 256 + threadIdx.x;
    if (t < KCB) g_hist[t] = 0;
}

__global__ void cnorm_kernel(const float* __restrict__ E) {
    int k = blockIdx.x * 256 + threadIdx.x;
    float s = 0.f;
#pragma unroll 8
    for (int d = 0; d < DIM; d++) {
        float e = E[d * KCB + k];
        s = fmaf(e, e, s);
    }
    g_cnorm[k] = s;
}

__global__ void splitX_kernel(const float* __restrict__ X) {
    int i = blockIdx.x * 256 + threadIdx.x;        // float4 index
    float4 x = ((const float4*)X)[i];
    __half2* p = (__half2*)(g_Xh + (size_t)i * 4);
    p[0] = __half2(__float2half(x.x), __float2half(x.y));
    p[1] = __half2(__float2half(x.z), __float2half(x.w));
}

// E transpose + fp16: E[d][k] -> g_Eh[k][d]
__global__ void splitE_kernel(const float* __restrict__ E) {
    __shared__ float t[32][33];
    int k0 = blockIdx.x * 32, d0 = blockIdx.y * 32;
#pragma unroll
    for (int i = 0; i < 32; i += 8)
        t[threadIdx.y + i][threadIdx.x] =
            E[(size_t)(d0 + threadIdx.y + i) * KCB + k0 + threadIdx.x];
    __syncthreads();
#pragma unroll
    for (int i = 0; i < 32; i += 8) {
        int k = k0 + threadIdx.y + i, d = d0 + threadIdx.x;
        g_Eh[(size_t)k * DIM + d] = __float2half(t[threadIdx.x][threadIdx.y + i]);
    }
}

// ---------------------------------------------------------------------------
// fp16 HMMA GEMM + argmax. 256 threads, 8 warps (2m x 4n), warp tile m64 x n32.
// A (128 rows x 256 fp16) resident; B streamed in 128-code x 128-dim chunks,
// double-buffered cp.async. 64 code-tiles; top-2 per partition, merge at end.
extern __shared__ char sm_arg[];

__device__ __forceinline__ void loadB_chunk(uint32_t sb, int tid, int g, int bf) {
    int nt = g >> 1, kc = g & 1;
    const char* base = (const char*)g_Eh + (size_t)nt * 128 * 512 + kc * 256;
    uint32_t sbase = sb + SM_B + bf * SB_BUF;
#pragma unroll
    for (int i = 0; i < 8; i++) {
        int idx = tid + 256 * i;            // 0..2047
        int c = idx >> 4, j = idx & 15;
        CP_ASYNC16(sbase + c * SB_BYTES + j * 16, base + (size_t)c * 512 + j * 16);
    }
}

__global__ void __launch_bounds__(256, 1)
argmax_mma_kernel() {
    uint32_t sb = smem_u32(sm_arg);
    const int tid  = threadIdx.x;
    const int lane = tid & 31, wid = tid >> 5;
    const int warp_m = wid & 1, warp_n = wid >> 1;
    const int m0 = blockIdx.x * 128;

    // A preload: 128 rows x 32 x 16B
#pragma unroll
    for (int i = 0; i < 16; i++) {
        int idx = tid + 256 * i;
        int r = idx >> 5, ch = idx & 31;
        CP_ASYNC16(sb + SM_A + r * SA_BYTES + ch * 16,
                   (const char*)g_Xh + (size_t)(m0 + r) * 512 + ch * 16);
    }
    loadB_chunk(sb, tid, 0, 0);
    CP_COMMIT();

    const uint32_t a_base = sb + SM_A
                          + (warp_m * 64 + (lane & 15)) * SA_BYTES
                          + (lane >> 4) * 16;
    const uint32_t b_addr0 = sb + SM_B
                           + (warp_n * 32 + (lane & 15)) * SB_BYTES + (lane >> 4) * 16;

    float acc[4][4][4];
#pragma unroll
    for (int mi = 0; mi < 4; mi++)
#pragma unroll
        for (int nj = 0; nj < 4; nj++)
#pragma unroll
            for (int q = 0; q < 4; q++) acc[mi][nj][q] = 0.f;

    float best[8], best2[8]; int bk[8];
#pragma unroll
    for (int s = 0; s < 8; s++) { best[s] = -3.4e38f; best2[s] = -3.4e38f; bk[s] = 0; }

    for (int g = 0; g < 128; g++) {
        int buf = g & 1;
        if (g + 1 < 128) {
            loadB_chunk(sb, tid, g + 1, buf ^ 1);
            CP_COMMIT();
            CP_WAIT1();
        } else {
            CP_WAIT0();
        }
        __syncthreads();

        const int kc = g & 1;
        const uint32_t ak = kc * 256;                     // byte offset in A row
        const uint32_t bb = b_addr0 + buf * SB_BUF;
#pragma unroll
        for (int kq = 0; kq < 8; kq++) {
            uint32_t bf[2][4];
#pragma unroll
            for (int jb = 0; jb < 2; jb++)
                ldsm4(bf[jb], bb + jb * (16 * SB_BYTES) + kq * 32);
#pragma unroll
            for (int mi = 0; mi < 4; mi++) {
                uint32_t af[4];
                ldsm4(af, a_base + mi * (16 * SA_BYTES) + ak + kq * 32);
                mma16816(acc[mi][0], af, bf[0][0], bf[0][2]);
                mma16816(acc[mi][1], af, bf[0][1], bf[0][3]);
                mma16816(acc[mi][2], af, bf[1][0], bf[1][2]);
                mma16816(acc[mi][3], af, bf[1][1], bf[1][3]);
            }
        }

        if (kc == 1) {                                    // tile epilogue
            const int nt = g >> 1;
            const int cb = nt * 128 + warp_n * 32 + (lane & 3) * 2;
            float cn[8];
#pragma unroll
            for (int nj = 0; nj < 4; nj++) {
                cn[nj * 2]     = __ldg(g_cnorm + cb + nj * 8);
                cn[nj * 2 + 1] = __ldg(g_cnorm + cb + nj * 8 + 1);
            }
#pragma unroll
            for (int mi = 0; mi < 4; mi++)
#pragma unroll
                for (int h = 0; h < 2; h++) {
                    const int s = mi * 2 + h;
                    float b1 = best[s], b2 = best2[s]; int kb = bk[s];
#pragma unroll
                    for (int nj = 0; nj < 4; nj++)
#pragma unroll
                        for (int c = 0; c < 2; c++) {
                            float v = fmaf(2.f, acc[mi][nj][h * 2 + c], -cn[nj * 2 + c]);
                            int k = cb + nj * 8 + c;
                            if (v > b1) { b2 = b1; b1 = v; kb = k; }
                            else if (v > b2) b2 = v;
                        }
                    best[s] = b1; best2[s] = b2; bk[s] = kb;
                }
#pragma unroll
            for (int mi = 0; mi < 4; mi++)
#pragma unroll
                for (int nj = 0; nj < 4; nj++)
#pragma unroll
                    for (int q = 0; q < 4; q++) acc[mi][nj][q] = 0.f;
        }
        __syncthreads();
    }

    // cross-partition reduce: 16 partitions per row; scratch in A region
    float* sB1 = (float*)(sm_arg);                 // 128*16 f32
    float* sB2 = sB1 + 2048;
    int*   sBK = (int*)(sB2 + 2048);
    const int part = warp_n * 4 + (lane & 3);
#pragma unroll
    for (int mi = 0; mi < 4; mi++)
#pragma unroll
        for (int h = 0; h < 2; h++) {
            int s = mi * 2 + h;
            int row = warp_m * 64 + mi * 16 + h * 8 + (lane >> 2);
            sB1[row * 16 + part] = best[s];
            sB2[row * 16 + part] = best2[s];
            sBK[row * 16 + part] = bk[s];
        }
    __syncthreads();
    if (tid < 128) {
        float B1 = -3.4e38f, B2 = -3.4e38f; int K1 = 0x7fffffff;
        for (int p = 0; p < 16; p++) {
            float v1 = sB1[tid * 16 + p], v2 = sB2[tid * 16 + p];
            int   k1 = sBK[tid * 16 + p];
            if (v1 > B1)       { B2 = B1; B1 = v1; K1 = k1; }
            else if (v1 == B1) { if (k1 < K1) K1 = k1; B2 = B1; }
            else if (v1 > B2)  { B2 = v1; }
            if (v2 > B2) B2 = v2;
        }
        g_idx[m0 + tid]  = K1;
        g_flag[m0 + tid] = (B1 - B2 < GAP_THR) ? 1 : 0;
    }
}

// ---------------------------------------------------------------------------
// exact fp32 rescore for flagged (small-gap) rows
__global__ void rescue_kernel(const float* __restrict__ X, const float* __restrict__ E) {
    __shared__ float xs[DIM];
    __shared__ float bv[256];
    __shared__ int   bkk[256];
    const int tid = threadIdx.x;
    for (int row = blockIdx.x; row < N_ROWS; row += gridDim.x) {
        if (!g_flag[row]) continue;
        xs[tid] = X[(size_t)row * DIM + tid];
        __syncthreads();
        float best = -3.4e38f; int bk = 0x7fffffff;
        for (int k = tid; k < KCB; k += 256) {
            float dot = 0.f;
#pragma unroll 8
            for (int d = 0; d < DIM; d++)
                dot = fmaf(xs[d], E[(size_t)d * KCB + k], dot);
            float v = fmaf(2.f, dot, -g_cnorm[k]);
            if (v > best) { best = v; bk = k; }
        }
        bv[tid] = best; bkk[tid] = bk;
        __syncthreads();
        for (int o = 128; o; o >>= 1) {
            if (tid < o) {
                float v2 = bv[tid + o]; int k2 = bkk[tid + o];
                if (v2 > bv[tid] || (v2 == bv[tid] && k2 < bkk[tid])) {
                    bv[tid] = v2; bkk[tid] = k2;
                }
            }
            __syncthreads();
        }
        if (tid == 0) g_idx[row] = bkk[0];
        __syncthreads();
    }
}

// ---------------------------------------------------------------------------
__global__ void gather_kernel(const float* __restrict__ X,
                              const float* __restrict__ E,
                              float* __restrict__ outq,
                              float* __restrict__ outidx) {
    const int warp = threadIdx.x >> 5;
    const int lane = threadIdx.x & 31;
    const int row  = blockIdx.x * 8 + warp;
    const int k    = g_idx[row];

    float ss = 0.f;
#pragma unroll
    for (int d = lane; d < DIM; d += 32) {
        float q = E[d * KCB + k];
        float x = X[row * DIM + d];
        outq[row * DIM + d] = q;
        float df = q - x;
        ss = fmaf(df, df, ss);
    }
#pragma unroll
    for (int o = 16; o; o >>= 1) ss += __shfl_xor_sync(0xffffffffu, ss, o);

    __shared__ float wss[8];
    if (lane == 0) {
        wss[warp] = ss;
        atomicAdd(&g_hist[k], 1);
        if (outidx) outidx[row] = (float)k;
    }
    __syncthreads();
    if (threadIdx.x == 0) {
        float s = 0.f;
        for (int w = 0; w < 8; w++) s += wss[w];
        g_partials[blockIdx.x] = s;
    }
}

__global__ void finalize_kernel(float* __restrict__ out_scalars) {
    __shared__ double sd[256];
    const int t = threadIdx.x;

    double s = 0.0;
    for (int i = t; i < NBLK_GATHER; i += 256) s += (double)g_partials[i];
    sd[t] = s; __syncthreads();
    for (int o = 128; o; o >>= 1) { if (t < o) sd[t] += sd[t + o]; __syncthreads(); }
    double sq = sd[0];
    __syncthreads();

    double e = 0.0;
    for (int k = t; k < KCB; k += 256) {
        float p = (float)g_hist[k] / (float)N_ROWS;
        e += (double)(p * logf(p + 1e-10f));
    }
    sd[t] = e; __syncthreads();
    for (int o = 128; o; o >>= 1) { if (t < o) sd[t] += sd[t + o]; __syncthreads(); }

    if (t == 0) {
        float mse = (float)(sq / (double)((long long)N_ROWS * DIM));
        float vq_loss = mse + 0.1f * mse;
        float entropy = -(float)sd[0];
        float usage_loss = -(entropy / logf((float)KCB));
        out_scalars[0] = vq_loss;
        out_scalars[1] = 0.1f * usage_loss;
    }
}

// ---------------------------------------------------------------------------
extern "C" void kernel_launch(void* const* d_in, const int* in_sizes, int n_in,
                              void* d_out, int out_size) {
    const float* X = (const float*)d_in[0];   // [32,32,32,256] f32
    const float* E = (const float*)d_in[1];   // [256, 8192] f32
    float* out = (float*)d_out;

    const int NQ = N_ROWS * DIM;
    float* outq   = out;
    float* outidx = (out_size >= NQ + N_ROWS)     ? out + NQ          : (float*)0;
    float* outs   = (out_size >= NQ + N_ROWS + 2) ? out + NQ + N_ROWS : (float*)0;

    cudaFuncSetAttribute(argmax_mma_kernel,
                         cudaFuncAttributeMaxDynamicSharedMemorySize, SMEM_TOTAL);

    zero_hist_kernel<<<32, 256>>>();
    cnorm_kernel<<<KCB / 256, 256>>>(E);
    splitX_kernel<<<8192, 256>>>(X);
    splitE_kernel<<<dim3(KCB / 32, DIM / 32), dim3(32, 8)>>>(E);
    argmax_mma_kernel<<<N_ROWS / 128, 256, SMEM_TOTAL>>>();
    rescue_kernel<<<256, 256>>>(X, E);
    gather_kernel<<<NBLK_GATHER, 256>>>(X, E, outq, outidx);
    if (outs) finalize_kernel<<<1, 256>>>(outs);
}

// round 6
// speedup vs baseline: 1.0334x; 1.0334x over previous
#include <cuda_runtime.h>
#include <cuda_fp16.h>
#include <math.h>
#include <stdint.h>

#define N_ROWS 32768
#define DIM    256
#define KCB    8192
#define NBLK_GATHER 4096
#define GAP_THR 5e-3f

// ---------------------------------------------------------------------------
// scratch (device globals; no cudaMalloc allowed)
__device__ __half g_Xh[(size_t)N_ROWS * DIM];
__device__ __half g_Eh[(size_t)KCB * DIM];     // transposed: [code][dim]
__device__ float g_cnorm[KCB];
__device__ int   g_idx[N_ROWS];
__device__ int   g_flag[N_ROWS];
__device__ int   g_hist[KCB];
__device__ float g_partials[NBLK_GATHER];

// ---------------------------------------------------------------------------
__device__ __forceinline__ uint32_t smem_u32(const void* p) {
    uint32_t a;
    asm("{ .reg .u64 t; cvta.to.shared.u64 t, %1; cvt.u32.u64 %0, t; }"
        : "=r"(a) : "l"(p));
    return a;
}

#define CP_ASYNC16(s, g) \
    asm volatile("cp.async.cg.shared.global [%0], [%1], 16;" :: "r"(s), "l"(g) : "memory")
#define CP_COMMIT()  asm volatile("cp.async.commit_group;" ::: "memory")
#define CP_WAIT1()   asm volatile("cp.async.wait_group 1;" ::: "memory")
#define CP_WAIT0()   asm volatile("cp.async.wait_group 0;" ::: "memory")

__device__ __forceinline__ void ldsm4(uint32_t* r, uint32_t addr) {
    asm volatile("ldmatrix.sync.aligned.m8n8.x4.shared.b16 {%0,%1,%2,%3}, [%4];"
                 : "=r"(r[0]), "=r"(r[1]), "=r"(r[2]), "=r"(r[3]) : "r"(addr));
}

__device__ __forceinline__ void mma16816(float* c, const uint32_t* a, uint32_t b0, uint32_t b1) {
    asm volatile(
        "mma.sync.aligned.m16n8k16.row.col.f32.f16.f16.f32 "
        "{%0,%1,%2,%3}, {%4,%5,%6,%7}, {%8,%9}, {%0,%1,%2,%3};"
        : "+f"(c[0]), "+f"(c[1]), "+f"(c[2]), "+f"(c[3])
        : "r"(a[0]), "r"(a[1]), "r"(a[2]), "r"(a[3]), "r"(b0), "r"(b1));
}

// smem layout: A 256 rows x 264 fp16 (stride 528B, 33 chunks ≡ 1 mod 8),
// B double-buffered 128 codes x 136 fp16 (stride 272B, 17 chunks ≡ 1 mod 8)
#define SA_BYTES 528
#define SB_BYTES 272
#define SM_A     0
#define SM_B     (256 * SA_BYTES)       // 135168
#define SB_BUF   (128 * SB_BYTES)       // 34816
#define SMEM_TOTAL (SM_B + 2 * SB_BUF)  // 204800

// ---------------------------------------------------------------------------
// cnorm + hist zero (merged so argmax is the 4th launch -> ncu captures it)
__global__ void cnorm_kernel(const float* __restrict__ E) {
    int k = blockIdx.x * 256 + threadIdx.x;
    g_hist[k] = 0;
    float s = 0.f;
#pragma unroll 8
    for (int d = 0; d < DIM; d++) {
        float e = E[d * KCB + k];
        s = fmaf(e, e, s);
    }
    g_cnorm[k] = s;
}

__global__ void splitX_kernel(const float* __restrict__ X) {
    int i = blockIdx.x * 256 + threadIdx.x;        // float4 index
    float4 x = ((const float4*)X)[i];
    __half2* p = (__half2*)(g_Xh + (size_t)i * 4);
    p[0] = __half2(__float2half(x.x), __float2half(x.y));
    p[1] = __half2(__float2half(x.z), __float2half(x.w));
}

// E transpose + fp16: E[d][k] -> g_Eh[k][d]
__global__ void splitE_kernel(const float* __restrict__ E) {
    __shared__ float t[32][33];
    int k0 = blockIdx.x * 32, d0 = blockIdx.y * 32;
#pragma unroll
    for (int i = 0; i < 32; i += 8)
        t[threadIdx.y + i][threadIdx.x] =
            E[(size_t)(d0 + threadIdx.y + i) * KCB + k0 + threadIdx.x];
    __syncthreads();
#pragma unroll
    for (int i = 0; i < 32; i += 8) {
        int k = k0 + threadIdx.y + i, d = d0 + threadIdx.x;
        g_Eh[(size_t)k * DIM + d] = __float2half(t[threadIdx.x][threadIdx.y + i]);
    }
}

// ---------------------------------------------------------------------------
// fp16 HMMA GEMM + argmax. 512 threads, 16 warps (4m x 4n), warp tile m64 x n32.
// A (256 rows x 256 fp16) resident; B streamed in 128-code x 128-dim chunks,
// double-buffered cp.async. 64 code-tiles; top-2 per partition, merge at end.
extern __shared__ char sm_arg[];

__device__ __forceinline__ void loadB_chunk(uint32_t sb, int tid, int g, int bf) {
    int nt = g >> 1, kc = g & 1;
    const char* base = (const char*)g_Eh + (size_t)nt * 128 * 512 + kc * 256;
    uint32_t sbase = sb + SM_B + bf * SB_BUF;
#pragma unroll
    for (int i = 0; i < 4; i++) {
        int idx = tid + 512 * i;            // 0..2047
        int c = idx >> 4, j = idx & 15;
        CP_ASYNC16(sbase + c * SB_BYTES + j * 16, base + (size_t)c * 512 + j * 16);
    }
}

__global__ void __launch_bounds__(512, 1)
argmax_mma_kernel() {
    uint32_t sb = smem_u32(sm_arg);
    const int tid  = threadIdx.x;
    const int lane = tid & 31, wid = tid >> 5;
    const int warp_m = wid & 3, warp_n = wid >> 2;
    const int m0 = blockIdx.x * 256;

    // A preload: 256 rows x 32 x 16B
#pragma unroll
    for (int i = 0; i < 16; i++) {
        int idx = tid + 512 * i;
        int r = idx >> 5, ch = idx & 31;
        CP_ASYNC16(sb + SM_A + r * SA_BYTES + ch * 16,
                   (const char*)g_Xh + (size_t)(m0 + r) * 512 + ch * 16);
    }
    loadB_chunk(sb, tid, 0, 0);
    CP_COMMIT();

    const uint32_t a_base = sb + SM_A
                          + (warp_m * 64 + (lane & 15)) * SA_BYTES
                          + (lane >> 4) * 16;
    const uint32_t b_addr0 = sb + SM_B
                           + (warp_n * 32 + (lane & 15)) * SB_BYTES + (lane >> 4) * 16;

    float acc[4][4][4];
#pragma unroll
    for (int mi = 0; mi < 4; mi++)
#pragma unroll
        for (int nj = 0; nj < 4; nj++)
#pragma unroll
            for (int q = 0; q < 4; q++) acc[mi][nj][q] = 0.f;

    float best[8], best2[8]; int bk[8];
#pragma unroll
    for (int s = 0; s < 8; s++) { best[s] = -3.4e38f; best2[s] = -3.4e38f; bk[s] = 0; }

    for (int g = 0; g < 128; g++) {
        int buf = g & 1;
        if (g + 1 < 128) {
            loadB_chunk(sb, tid, g + 1, buf ^ 1);
            CP_COMMIT();
            CP_WAIT1();
        } else {
            CP_WAIT0();
        }
        __syncthreads();

        const int kc = g & 1;
        const uint32_t ak = kc * 256;                     // byte offset in A row
        const uint32_t bb = b_addr0 + buf * SB_BUF;
#pragma unroll
        for (int kq = 0; kq < 8; kq++) {
            uint32_t bf[2][4];
#pragma unroll
            for (int jb = 0; jb < 2; jb++)
                ldsm4(bf[jb], bb + jb * (16 * SB_BYTES) + kq * 32);
#pragma unroll
            for (int mi = 0; mi < 4; mi++) {
                uint32_t af[4];
                ldsm4(af, a_base + mi * (16 * SA_BYTES) + ak + kq * 32);
                mma16816(acc[mi][0], af, bf[0][0], bf[0][2]);
                mma16816(acc[mi][1], af, bf[0][1], bf[0][3]);
                mma16816(acc[mi][2], af, bf[1][0], bf[1][2]);
                mma16816(acc[mi][3], af, bf[1][1], bf[1][3]);
            }
        }

        if (kc == 1) {                                    // tile epilogue
            const int nt = g >> 1;
            const int cb = nt * 128 + warp_n * 32 + (lane & 3) * 2;
            float cn[8];
#pragma unroll
            for (int nj = 0; nj < 4; nj++) {
                cn[nj * 2]     = __ldg(g_cnorm + cb + nj * 8);
                cn[nj * 2 + 1] = __ldg(g_cnorm + cb + nj * 8 + 1);
            }
#pragma unroll
            for (int mi = 0; mi < 4; mi++)
#pragma unroll
                for (int h = 0; h < 2; h++) {
                    const int s = mi * 2 + h;
                    float b1 = best[s], b2 = best2[s]; int kb = bk[s];
#pragma unroll
                    for (int nj = 0; nj < 4; nj++)
#pragma unroll
                        for (int c = 0; c < 2; c++) {
                            float v = fmaf(2.f, acc[mi][nj][h * 2 + c], -cn[nj * 2 + c]);
                            int k = cb + nj * 8 + c;
                            if (v > b1) { b2 = b1; b1 = v; kb = k; }
                            else if (v > b2) b2 = v;
                        }
                    best[s] = b1; best2[s] = b2; bk[s] = kb;
                }
#pragma unroll
            for (int mi = 0; mi < 4; mi++)
#pragma unroll
                for (int nj = 0; nj < 4; nj++)
#pragma unroll
                    for (int q = 0; q < 4; q++) acc[mi][nj][q] = 0.f;
        }
        __syncthreads();
    }

    // cross-partition reduce: 16 partitions per row; scratch in A region
    float* sB1 = (float*)(sm_arg);                 // 256*16 f32
    float* sB2 = sB1 + 4096;
    int*   sBK = (int*)(sB2 + 4096);
    const int part = warp_n * 4 + (lane & 3);
#pragma unroll
    for (int mi = 0; mi < 4; mi++)
#pragma unroll
        for (int h = 0; h < 2; h++) {
            int s = mi * 2 + h;
            int row = warp_m * 64 + mi * 16 + h * 8 + (lane >> 2);
            sB1[row * 16 + part] = best[s];
            sB2[row * 16 + part] = best2[s];
            sBK[row * 16 + part] = bk[s];
        }
    __syncthreads();
    if (tid < 256) {
        float B1 = -3.4e38f, B2 = -3.4e38f; int K1 = 0x7fffffff;
        for (int p = 0; p < 16; p++) {
            float v1 = sB1[tid * 16 + p], v2 = sB2[tid * 16 + p];
            int   k1 = sBK[tid * 16 + p];
            if (v1 > B1)       { B2 = B1; B1 = v1; K1 = k1; }
            else if (v1 == B1) { if (k1 < K1) K1 = k1; B2 = B1; }
            else if (v1 > B2)  { B2 = v1; }
            if (v2 > B2) B2 = v2;
        }
        g_idx[m0 + tid]  = K1;
        g_flag[m0 + tid] = (B1 - B2 < GAP_THR) ? 1 : 0;
    }
}

// ---------------------------------------------------------------------------
// exact fp32 rescore for flagged (small-gap) rows
__global__ void rescue_kernel(const float* __restrict__ X, const float* __restrict__ E) {
    __shared__ float xs[DIM];
    __shared__ float bv[256];
    __shared__ int   bkk[256];
    const int tid = threadIdx.x;
    for (int row = blockIdx.x; row < N_ROWS; row += gridDim.x) {
        if (!g_flag[row]) continue;
        xs[tid] = X[(size_t)row * DIM + tid];
        __syncthreads();
        float best = -3.4e38f; int bk = 0x7fffffff;
        for (int k = tid; k < KCB; k += 256) {
            float dot = 0.f;
#pragma unroll 8
            for (int d = 0; d < DIM; d++)
                dot = fmaf(xs[d], E[(size_t)d * KCB + k], dot);
            float v = fmaf(2.f, dot, -g_cnorm[k]);
            if (v > best) { best = v; bk = k; }
        }
        bv[tid] = best; bkk[tid] = bk;
        __syncthreads();
        for (int o = 128; o; o >>= 1) {
            if (tid < o) {
                float v2 = bv[tid + o]; int k2 = bkk[tid + o];
                if (v2 > bv[tid] || (v2 == bv[tid] && k2 < bkk[tid])) {
                    bv[tid] = v2; bkk[tid] = k2;
                }
            }
            __syncthreads();
        }
        if (tid == 0) g_idx[row] = bkk[0];
        __syncthreads();
    }
}

// ---------------------------------------------------------------------------
__global__ void gather_kernel(const float* __restrict__ X,
                              const float* __restrict__ E,
                              float* __restrict__ outq,
                              float* __restrict__ outidx) {
    const int warp = threadIdx.x >> 5;
    const int lane = threadIdx.x & 31;
    const int row  = blockIdx.x * 8 + warp;
    const int k    = g_idx[row];

    float ss = 0.f;
#pragma unroll
    for (int d = lane; d < DIM; d += 32) {
        float q = E[d * KCB + k];
        float x = X[row * DIM + d];
        outq[row * DIM + d] = q;
        float df = q - x;
        ss = fmaf(df, df, ss);
    }
#pragma unroll
    for (int o = 16; o; o >>= 1) ss += __shfl_xor_sync(0xffffffffu, ss, o);

    __shared__ float wss[8];
    if (lane == 0) {
        wss[warp] = ss;
        atomicAdd(&g_hist[k], 1);
        if (outidx) outidx[row] = (float)k;
    }
    __syncthreads();
    if (threadIdx.x == 0) {
        float s = 0.f;
        for (int w = 0; w < 8; w++) s += wss[w];
        g_partials[blockIdx.x] = s;
    }
}

__global__ void finalize_kernel(float* __restrict__ out_scalars) {
    __shared__ double sd[256];
    const int t = threadIdx.x;

    double s = 0.0;
    for (int i = t; i < NBLK_GATHER; i += 256) s += (double)g_partials[i];
    sd[t] = s; __syncthreads();
    for (int o = 128; o; o >>= 1) { if (t < o) sd[t] += sd[t + o]; __syncthreads(); }
    double sq = sd[0];
    __syncthreads();

    double e = 0.0;
    for (int k = t; k < KCB; k += 256) {
        float p = (float)g_hist[k] / (float)N_ROWS;
        e += (double)(p * logf(p + 1e-10f));
    }
    sd[t] = e; __syncthreads();
    for (int o = 128; o; o >>= 1) { if (t < o) sd[t] += sd[t + o]; __syncthreads(); }

    if (t == 0) {
        float mse = (float)(sq / (double)((long long)N_ROWS * DIM));
        float vq_loss = mse + 0.1f * mse;
        float entropy = -(float)sd[0];
        float usage_loss = -(entropy / logf((float)KCB));
        out_scalars[0] = vq_loss;
        out_scalars[1] = 0.1f * usage_loss;
    }
}

// ---------------------------------------------------------------------------
extern "C" void kernel_launch(void* const* d_in, const int* in_sizes, int n_in,
                              void* d_out, int out_size) {
    const float* X = (const float*)d_in[0];   // [32,32,32,256] f32
    const float* E = (const float*)d_in[1];   // [256, 8192] f32
    float* out = (float*)d_out;

    const int NQ = N_ROWS * DIM;
    float* outq   = out;
    float* outidx = (out_size >= NQ + N_ROWS)     ? out + NQ          : (float*)0;
    float* outs   = (out_size >= NQ + N_ROWS + 2) ? out + NQ + N_ROWS : (float*)0;

    cudaFuncSetAttribute(argmax_mma_kernel,
                         cudaFuncAttributeMaxDynamicSharedMemorySize, SMEM_TOTAL);

    // launch order chosen so argmax_mma_kernel is the 4th launch (ncu captures #4)
    cnorm_kernel<<<KCB / 256, 256>>>(E);
    splitX_kernel<<<8192, 256>>>(X);
    splitE_kernel<<<dim3(KCB / 32, DIM / 32), dim3(32, 8)>>>(E);
    argmax_mma_kernel<<<N_ROWS / 256, 512, SMEM_TOTAL>>>();
    rescue_kernel<<<256, 256>>>(X, E);
    gather_kernel<<<NBLK_GATHER, 256>>>(X, E, outq, outidx);
    if (outs) finalize_kernel<<<1, 256>>>(outs);
}

// round 7
// speedup vs baseline: 3.2141x; 3.1102x over previous
#include <cuda_runtime.h>
#include <cuda_fp16.h>
#include <math.h>
#include <stdint.h>

#define N_ROWS 32768
#define DIM    256
#define KCB    8192
#define NBLK_GATHER 4096
#define GAP_THR 5e-3f

// ---------------------------------------------------------------------------
// scratch (device globals; no cudaMalloc allowed)
__device__ __half g_Xh[(size_t)N_ROWS * DIM];
__device__ __half g_Eh[(size_t)KCB * DIM];     // transposed: [code][dim]
__device__ float g_cnorm[KCB];
__device__ int   g_idx[N_ROWS];
__device__ int   g_hist[KCB];
__device__ float g_partials[NBLK_GATHER];
__device__ int   g_cnt;                         // flagged-row count
__device__ int   g_list[N_ROWS];                // flagged-row list
__device__ unsigned long long g_best64[N_ROWS]; // packed (score,8191-k) per flagged row

// ---------------------------------------------------------------------------
__device__ __forceinline__ uint32_t smem_u32(const void* p) {
    uint32_t a;
    asm("{ .reg .u64 t; cvta.to.shared.u64 t, %1; cvt.u32.u64 %0, t; }"
        : "=r"(a) : "l"(p));
    return a;
}

#define CP_ASYNC16(s, g) \
    asm volatile("cp.async.cg.shared.global [%0], [%1], 16;" :: "r"(s), "l"(g) : "memory")
#define CP_COMMIT()  asm volatile("cp.async.commit_group;" ::: "memory")
#define CP_WAIT1()   asm volatile("cp.async.wait_group 1;" ::: "memory")
#define CP_WAIT0()   asm volatile("cp.async.wait_group 0;" ::: "memory")

__device__ __forceinline__ void ldsm4(uint32_t* r, uint32_t addr) {
    asm volatile("ldmatrix.sync.aligned.m8n8.x4.shared.b16 {%0,%1,%2,%3}, [%4];"
                 : "=r"(r[0]), "=r"(r[1]), "=r"(r[2]), "=r"(r[3]) : "r"(addr));
}

__device__ __forceinline__ void mma16816(float* c, const uint32_t* a, uint32_t b0, uint32_t b1) {
    asm volatile(
        "mma.sync.aligned.m16n8k16.row.col.f32.f16.f16.f32 "
        "{%0,%1,%2,%3}, {%4,%5,%6,%7}, {%8,%9}, {%0,%1,%2,%3};"
        : "+f"(c[0]), "+f"(c[1]), "+f"(c[2]), "+f"(c[3])
        : "r"(a[0]), "r"(a[1]), "r"(a[2]), "r"(a[3]), "r"(b0), "r"(b1));
}

// monotone float encoding for u64 max-merge; low word 8191-k (tie -> lowest k)
__device__ __forceinline__ unsigned long long pack_vk(float v, int k) {
    uint32_t b = __float_as_uint(v);
    b = (b & 0x80000000u) ? ~b : (b | 0x80000000u);
    return ((unsigned long long)b << 32) | (uint32_t)(KCB - 1 - k);
}

// smem layout: A 256 rows x 264 fp16 (stride 528B, 33 chunks ≡ 1 mod 8),
// B double-buffered 128 codes x 136 fp16 (stride 272B, 17 chunks ≡ 1 mod 8)
#define SA_BYTES 528
#define SB_BYTES 272
#define SM_A     0
#define SM_B     (256 * SA_BYTES)       // 135168
#define SB_BUF   (128 * SB_BYTES)       // 34816
#define SMEM_TOTAL (SM_B + 2 * SB_BUF)  // 204800

// ---------------------------------------------------------------------------
// cnorm + hist/cnt zero (argmax stays launch #4 for ncu)
__global__ void cnorm_kernel(const float* __restrict__ E) {
    int k = blockIdx.x * 256 + threadIdx.x;
    g_hist[k] = 0;
    if (k == 0) g_cnt = 0;
    float s = 0.f;
#pragma unroll 8
    for (int d = 0; d < DIM; d++) {
        float e = E[d * KCB + k];
        s = fmaf(e, e, s);
    }
    g_cnorm[k] = s;
}

__global__ void splitX_kernel(const float* __restrict__ X) {
    int i = blockIdx.x * 256 + threadIdx.x;        // float4 index
    float4 x = ((const float4*)X)[i];
    __half2* p = (__half2*)(g_Xh + (size_t)i * 4);
    p[0] = __half2(__float2half(x.x), __float2half(x.y));
    p[1] = __half2(__float2half(x.z), __float2half(x.w));
}

// E transpose + fp16: E[d][k] -> g_Eh[k][d]
__global__ void splitE_kernel(const float* __restrict__ E) {
    __shared__ float t[32][33];
    int k0 = blockIdx.x * 32, d0 = blockIdx.y * 32;
#pragma unroll
    for (int i = 0; i < 32; i += 8)
        t[threadIdx.y + i][threadIdx.x] =
            E[(size_t)(d0 + threadIdx.y + i) * KCB + k0 + threadIdx.x];
    __syncthreads();
#pragma unroll
    for (int i = 0; i < 32; i += 8) {
        int k = k0 + threadIdx.y + i, d = d0 + threadIdx.x;
        g_Eh[(size_t)k * DIM + d] = __float2half(t[threadIdx.x][threadIdx.y + i]);
    }
}

// ---------------------------------------------------------------------------
// fp16 HMMA GEMM + argmax. 512 threads, 16 warps (4m x 4n), warp tile m64 x n32.
extern __shared__ char sm_arg[];

__device__ __forceinline__ void loadB_chunk(uint32_t sb, int tid, int g, int bf) {
    int nt = g >> 1, kc = g & 1;
    const char* base = (const char*)g_Eh + (size_t)nt * 128 * 512 + kc * 256;
    uint32_t sbase = sb + SM_B + bf * SB_BUF;
#pragma unroll
    for (int i = 0; i < 4; i++) {
        int idx = tid + 512 * i;            // 0..2047
        int c = idx >> 4, j = idx & 15;
        CP_ASYNC16(sbase + c * SB_BYTES + j * 16, base + (size_t)c * 512 + j * 16);
    }
}

__global__ void __launch_bounds__(512, 1)
argmax_mma_kernel() {
    uint32_t sb = smem_u32(sm_arg);
    const int tid  = threadIdx.x;
    const int lane = tid & 31, wid = tid >> 5;
    const int warp_m = wid & 3, warp_n = wid >> 2;
    const int m0 = blockIdx.x * 256;

    // A preload: 256 rows x 32 x 16B
#pragma unroll
    for (int i = 0; i < 16; i++) {
        int idx = tid + 512 * i;
        int r = idx >> 5, ch = idx & 31;
        CP_ASYNC16(sb + SM_A + r * SA_BYTES + ch * 16,
                   (const char*)g_Xh + (size_t)(m0 + r) * 512 + ch * 16);
    }
    loadB_chunk(sb, tid, 0, 0);
    CP_COMMIT();

    const uint32_t a_base = sb + SM_A
                          + (warp_m * 64 + (lane & 15)) * SA_BYTES
                          + (lane >> 4) * 16;
    const uint32_t b_addr0 = sb + SM_B
                           + (warp_n * 32 + (lane & 15)) * SB_BYTES + (lane >> 4) * 16;

    float acc[4][4][4];
#pragma unroll
    for (int mi = 0; mi < 4; mi++)
#pragma unroll
        for (int nj = 0; nj < 4; nj++)
#pragma unroll
            for (int q = 0; q < 4; q++) acc[mi][nj][q] = 0.f;

    float best[8], best2[8]; int bk[8];
#pragma unroll
    for (int s = 0; s < 8; s++) { best[s] = -3.4e38f; best2[s] = -3.4e38f; bk[s] = 0; }

    for (int g = 0; g < 128; g++) {
        int buf = g & 1;
        if (g + 1 < 128) {
            loadB_chunk(sb, tid, g + 1, buf ^ 1);
            CP_COMMIT();
            CP_WAIT1();
        } else {
            CP_WAIT0();
        }
        __syncthreads();

        const int kc = g & 1;
        const uint32_t ak = kc * 256;                     // byte offset in A row
        const uint32_t bb = b_addr0 + buf * SB_BUF;
#pragma unroll
        for (int kq = 0; kq < 8; kq++) {
            uint32_t bf[2][4];
#pragma unroll
            for (int jb = 0; jb < 2; jb++)
                ldsm4(bf[jb], bb + jb * (16 * SB_BYTES) + kq * 32);
#pragma unroll
            for (int mi = 0; mi < 4; mi++) {
                uint32_t af[4];
                ldsm4(af, a_base + mi * (16 * SA_BYTES) + ak + kq * 32);
                mma16816(acc[mi][0], af, bf[0][0], bf[0][2]);
                mma16816(acc[mi][1], af, bf[0][1], bf[0][3]);
                mma16816(acc[mi][2], af, bf[1][0], bf[1][2]);
                mma16816(acc[mi][3], af, bf[1][1], bf[1][3]);
            }
        }

        if (kc == 1) {                                    // tile epilogue
            const int nt = g >> 1;
            const int cb = nt * 128 + warp_n * 32 + (lane & 3) * 2;
            float cn[8];
#pragma unroll
            for (int nj = 0; nj < 4; nj++) {
                cn[nj * 2]     = __ldg(g_cnorm + cb + nj * 8);
                cn[nj * 2 + 1] = __ldg(g_cnorm + cb + nj * 8 + 1);
            }
#pragma unroll
            for (int mi = 0; mi < 4; mi++)
#pragma unroll
                for (int h = 0; h < 2; h++) {
                    const int s = mi * 2 + h;
                    float b1 = best[s], b2 = best2[s]; int kb = bk[s];
#pragma unroll
                    for (int nj = 0; nj < 4; nj++)
#pragma unroll
                        for (int c = 0; c < 2; c++) {
                            float v = fmaf(2.f, acc[mi][nj][h * 2 + c], -cn[nj * 2 + c]);
                            int k = cb + nj * 8 + c;
                            if (v > b1) { b2 = b1; b1 = v; kb = k; }
                            else if (v > b2) b2 = v;
                        }
                    best[s] = b1; best2[s] = b2; bk[s] = kb;
                }
#pragma unroll
            for (int mi = 0; mi < 4; mi++)
#pragma unroll
                for (int nj = 0; nj < 4; nj++)
#pragma unroll
                    for (int q = 0; q < 4; q++) acc[mi][nj][q] = 0.f;
        }
        __syncthreads();
    }

    // cross-partition reduce: 16 partitions per row; scratch in A region
    float* sB1 = (float*)(sm_arg);                 // 256*16 f32
    float* sB2 = sB1 + 4096;
    int*   sBK = (int*)(sB2 + 4096);
    const int part = warp_n * 4 + (lane & 3);
#pragma unroll
    for (int mi = 0; mi < 4; mi++)
#pragma unroll
        for (int h = 0; h < 2; h++) {
            int s = mi * 2 + h;
            int row = warp_m * 64 + mi * 16 + h * 8 + (lane >> 2);
            sB1[row * 16 + part] = best[s];
            sB2[row * 16 + part] = best2[s];
            sBK[row * 16 + part] = bk[s];
        }
    __syncthreads();
    if (tid < 256) {
        float B1 = -3.4e38f, B2 = -3.4e38f; int K1 = 0x7fffffff;
        for (int p = 0; p < 16; p++) {
            float v1 = sB1[tid * 16 + p], v2 = sB2[tid * 16 + p];
            int   k1 = sBK[tid * 16 + p];
            if (v1 > B1)       { B2 = B1; B1 = v1; K1 = k1; }
            else if (v1 == B1) { if (k1 < K1) K1 = k1; B2 = B1; }
            else if (v1 > B2)  { B2 = v1; }
            if (v2 > B2) B2 = v2;
        }
        g_idx[m0 + tid] = K1;
        if (B1 - B2 < GAP_THR) {                 // flag -> compacted list
            int p = atomicAdd(&g_cnt, 1);
            g_list[p] = m0 + tid;
            g_best64[m0 + tid] = 0ULL;
        }
    }
}

// ---------------------------------------------------------------------------
// batched exact fp32 rescore: 4 code-quarters x 64 row-slots, 8 rows/batch.
// merge via atomicMax on packed (score, 8191-k): deterministic, tie->lowest k.
__global__ void __launch_bounds__(256)
rescue_kernel(const float* __restrict__ X, const float* __restrict__ E) {
    __shared__ float xs[8][DIM];      // 8 KB
    __shared__ int   rows_s[8];
    const int tid  = threadIdx.x;
    const int lane = tid & 31;
    const int cq = blockIdx.x & 3;    // 2048-code quarter
    const int rs = blockIdx.x >> 2;   // 0..63 row slot
    const int cnt = g_cnt;

    for (int b = rs; b * 8 < cnt; b += 64) {
        const int base = b * 8;
        const int nv = min(8, cnt - base);
        if (tid < nv) rows_s[tid] = g_list[base + tid];
        __syncthreads();
        for (int i = tid; i < nv * DIM; i += 256) {
            int r = i >> 8, d = i & 255;
            xs[r][d] = X[(size_t)rows_s[r] * DIM + d];
        }
        __syncthreads();

#pragma unroll 1
        for (int i = 0; i < 8; i++) {
            const int kk = cq * 2048 + tid + 256 * i;
            float a0 = 0.f, a1 = 0.f, a2 = 0.f, a3 = 0.f;
            float a4 = 0.f, a5 = 0.f, a6 = 0.f, a7 = 0.f;
#pragma unroll 8
            for (int d = 0; d < DIM; d++) {
                float e = E[d * KCB + kk];
                a0 = fmaf(e, xs[0][d], a0);
                a1 = fmaf(e, xs[1][d], a1);
                a2 = fmaf(e, xs[2][d], a2);
                a3 = fmaf(e, xs[3][d], a3);
                a4 = fmaf(e, xs[4][d], a4);
                a5 = fmaf(e, xs[5][d], a5);
                a6 = fmaf(e, xs[6][d], a6);
                a7 = fmaf(e, xs[7][d], a7);
            }
            const float c = g_cnorm[kk];
            float accs[8] = {a0, a1, a2, a3, a4, a5, a6, a7};
#pragma unroll 1
            for (int r = 0; r < nv; r++) {
                float v = fmaf(2.f, accs[r], -c);
                unsigned long long u = pack_vk(v, kk);
#pragma unroll
                for (int o = 16; o; o >>= 1) {
                    unsigned long long w = __shfl_xor_sync(0xffffffffu, u, o);
                    if (w > u) u = w;
                }
                if (lane == 0) atomicMax(&g_best64[rows_s[r]], u);
            }
        }
        __syncthreads();
    }
}

__global__ void fixup_kernel() {
    int idx = blockIdx.x * 256 + threadIdx.x;
    if (idx < g_cnt) {
        int row = g_list[idx];
        unsigned long long u = g_best64[row];
        g_idx[row] = KCB - 1 - (int)(u & 0xFFFFFFFFu);
    }
}

// ---------------------------------------------------------------------------
__global__ void gather_kernel(const float* __restrict__ X,
                              const float* __restrict__ E,
                              float* __restrict__ outq,
                              float* __restrict__ outidx) {
    const int warp = threadIdx.x >> 5;
    const int lane = threadIdx.x & 31;
    const int row  = blockIdx.x * 8 + warp;
    const int k    = g_idx[row];

    float ss = 0.f;
#pragma unroll
    for (int d = lane; d < DIM; d += 32) {
        float q = E[d * KCB + k];
        float x = X[row * DIM + d];
        outq[row * DIM + d] = q;
        float df = q - x;
        ss = fmaf(df, df, ss);
    }
#pragma unroll
    for (int o = 16; o; o >>= 1) ss += __shfl_xor_sync(0xffffffffu, ss, o);

    __shared__ float wss[8];
    if (lane == 0) {
        wss[warp] = ss;
        atomicAdd(&g_hist[k], 1);
        if (outidx) outidx[row] = (float)k;
    }
    __syncthreads();
    if (threadIdx.x == 0) {
        float s = 0.f;
        for (int w = 0; w < 8; w++) s += wss[w];
        g_partials[blockIdx.x] = s;
    }
}

__global__ void finalize_kernel(float* __restrict__ out_scalars) {
    __shared__ double sd[256];
    const int t = threadIdx.x;

    double s = 0.0;
    for (int i = t; i < NBLK_GATHER; i += 256) s += (double)g_partials[i];
    sd[t] = s; __syncthreads();
    for (int o = 128; o; o >>= 1) { if (t < o) sd[t] += sd[t + o]; __syncthreads(); }
    double sq = sd[0];
    __syncthreads();

    double e = 0.0;
    for (int k = t; k < KCB; k += 256) {
        float p = (float)g_hist[k] / (float)N_ROWS;
        e += (double)(p * logf(p + 1e-10f));
    }
    sd[t] = e; __syncthreads();
    for (int o = 128; o; o >>= 1) { if (t < o) sd[t] += sd[t + o]; __syncthreads(); }

    if (t == 0) {
        float mse = (float)(sq / (double)((long long)N_ROWS * DIM));
        float vq_loss = mse + 0.1f * mse;
        float entropy = -(float)sd[0];
        float usage_loss = -(entropy / logf((float)KCB));
        out_scalars[0] = vq_loss;
        out_scalars[1] = 0.1f * usage_loss;
    }
}

// ---------------------------------------------------------------------------
extern "C" void kernel_launch(void* const* d_in, const int* in_sizes, int n_in,
                              void* d_out, int out_size) {
    const float* X = (const float*)d_in[0];   // [32,32,32,256] f32
    const float* E = (const float*)d_in[1];   // [256, 8192] f32
    float* out = (float*)d_out;

    const int NQ = N_ROWS * DIM;
    float* outq   = out;
    float* outidx = (out_size >= NQ + N_ROWS)     ? out + NQ          : (float*)0;
    float* outs   = (out_size >= NQ + N_ROWS + 2) ? out + NQ + N_ROWS : (float*)0;

    cudaFuncSetAttribute(argmax_mma_kernel,
                         cudaFuncAttributeMaxDynamicSharedMemorySize, SMEM_TOTAL);

    // argmax_mma_kernel stays the 4th launch (ncu captures #4)
    cnorm_kernel<<<KCB / 256, 256>>>(E);
    splitX_kernel<<<8192, 256>>>(X);
    splitE_kernel<<<dim3(KCB / 32, DIM / 32), dim3(32, 8)>>>(E);
    argmax_mma_kernel<<<N_ROWS / 256, 512, SMEM_TOTAL>>>();
    rescue_kernel<<<256, 256>>>(X, E);
    fixup_kernel<<<N_ROWS / 256, 256>>>();
    gather_kernel<<<NBLK_GATHER, 256>>>(X, E, outq, outidx);
    if (outs) finalize_kernel<<<1, 256>>>(outs);
}